// round 7
// baseline (speedup 1.0000x reference)
#include <cuda_runtime.h>
#include <cuda_bf16.h>

// LDDMM variational evolve, Gaussian kernel sigma=0.1 (N=8192, D=3).
//   p      = clamp(mom, -1, 1)
//   K_ij   = exp(-50 |x_i - x_j|^2)
//   dcp_i  = sum_j K_ij p_j
//   dmom_i = 100 * ( x_i * sum_j W_ij - sum_j W_ij x_j ),  W_ij = K_ij (p_i.p_j)
//
// R7: fma-pipe (the measured bottleneck, rt=3 bank-limited packed FMA) cut from
//     ~25 to 21 cyc/2pairs:
//     - f32x2 lanes pack TWO j's; accumulators are j-parity partial sums, so
//       each accumulation fma2 retires 2 pairs.
//     - K = Ei * G with G = ex2(cj + xi.xj') on CENTERED coords (x-0.5):
//       Ei factors out of all j-sums -> applied once in epilogue; the
//       per-pair add2(ai) disappears. Centering bounds G <= 2^54 (no overflow).
//     - single fused kernel: last CTA per i-block (atomic counter) reduces the
//       32 split partials and writes the output. Deterministic fixed-order sum.

#define TI      64
#define IPT     2
#define IPB     128          // i's per block
#define JT      128          // j's per smem tile
#define JP      64           // j-pairs per tile
#define SPLITJ  32
#define MAXN    8192
#define NBLK    (MAXN/IPB)   // 64 i-blocks
#define L2E     1.4426950408889634f

typedef unsigned long long u64;

// partials: [i][split][8]  (7 used: dcx dcy dcz wxx | wxy wxz row pad)
__device__ float g_part[MAXN * SPLITJ * 8];
__device__ int   g_cnt[NBLK];   // zero-init; self-resetting

__device__ __forceinline__ u64 pack2(float lo, float hi) {
    u64 r; asm("mov.b64 %0, {%1, %2};" : "=l"(r) : "f"(lo), "f"(hi)); return r;
}
__device__ __forceinline__ void unpack2(u64 v, float& lo, float& hi) {
    asm("mov.b64 {%0, %1}, %2;" : "=f"(lo), "=f"(hi) : "l"(v));
}
__device__ __forceinline__ u64 fma2(u64 a, u64 b, u64 c) {
    u64 d; asm("fma.rn.f32x2 %0, %1, %2, %3;" : "=l"(d) : "l"(a), "l"(b), "l"(c)); return d;
}
__device__ __forceinline__ u64 mul2(u64 a, u64 b) {
    u64 d; asm("mul.rn.f32x2 %0, %1, %2;" : "=l"(d) : "l"(a), "l"(b)); return d;
}
__device__ __forceinline__ u64 add2(u64 a, u64 b) {
    u64 d; asm("add.rn.f32x2 %0, %1, %2;" : "=l"(d) : "l"(a), "l"(b)); return d;
}
__device__ __forceinline__ float ex2a(float x) {
    float y; asm("ex2.approx.f32 %0, %1;" : "=f"(y) : "f"(x)); return y;
}
__device__ __forceinline__ float clamp1(float v) {
    return fminf(fmaxf(v, -1.f), 1.f);
}

__global__ void __launch_bounds__(TI)
lddmm_fused(const float* __restrict__ mom,
            const float* __restrict__ cp,
            float* __restrict__ out,
            int N)
{
    // per j-pair: sXY=((x1,x2),(y1,y2)) sZC=((z1,z2),(c1,c2))
    //             sPA=((px1,px2),(py1,py2)) sPB=((pz1,pz2),-)
    __shared__ ulonglong2 sXY[JP], sZC[JP], sPA[JP], sPB[JP];
    __shared__ int sLast;

    const int bx = blockIdx.x;           // i-block
    const int jc = blockIdx.y;           // j-split
    const int jchunk = N / SPLITJ;       // 256
    const int j0 = jc * jchunk;
    const int tid = threadIdx.x;

    const float c100 = 100.0f * L2E;
    const float cm50 = -50.0f * L2E;

    // per-i state (centered coords)
    u64 X0[IPT], X1[IPT], X2[IPT];       // (c100*xi_c, c100*xi_c)
    u64 P0[IPT], P1[IPT], P2[IPT];       // (pi_c, pi_c)
    float Ei[IPT];
    u64 awx[IPT], awy[IPT], awz[IPT];    // j-parity sums of w*xj_c
    u64 adx[IPT], ady[IPT], adz[IPT];    // j-parity sums of G*pj_c
    u64 arw[IPT];                        // j-parity sums of w

    #pragma unroll
    for (int q = 0; q < IPT; q++) {
        int i = bx * IPB + q * TI + tid;
        float xx = cp[3*i+0] - 0.5f, xy = cp[3*i+1] - 0.5f, xz = cp[3*i+2] - 0.5f;
        float px = clamp1(mom[3*i+0]), py = clamp1(mom[3*i+1]), pz = clamp1(mom[3*i+2]);
        float sq = fmaf(xx, xx, fmaf(xy, xy, xz * xz));
        Ei[q] = ex2a(cm50 * sq);
        X0[q] = pack2(c100 * xx, c100 * xx);
        X1[q] = pack2(c100 * xy, c100 * xy);
        X2[q] = pack2(c100 * xz, c100 * xz);
        P0[q] = pack2(px, px);
        P1[q] = pack2(py, py);
        P2[q] = pack2(pz, pz);
        awx[q] = awy[q] = awz[q] = 0;
        adx[q] = ady[q] = adz[q] = 0;
        arw[q] = 0;
    }

    for (int jt = j0; jt < j0 + jchunk; jt += JT) {
        __syncthreads();
        {   // thread t stages j-pair (jt+2t, jt+2t+1);  TI == JP
            int j = jt + 2 * tid;
            float x1 = cp[3*j+0] - 0.5f, y1 = cp[3*j+1] - 0.5f, z1 = cp[3*j+2] - 0.5f;
            float x2 = cp[3*j+3] - 0.5f, y2 = cp[3*j+4] - 0.5f, z2 = cp[3*j+5] - 0.5f;
            float px1 = clamp1(mom[3*j+0]), py1 = clamp1(mom[3*j+1]), pz1 = clamp1(mom[3*j+2]);
            float px2 = clamp1(mom[3*j+3]), py2 = clamp1(mom[3*j+4]), pz2 = clamp1(mom[3*j+5]);
            float c1 = cm50 * fmaf(x1, x1, fmaf(y1, y1, z1 * z1));
            float c2 = cm50 * fmaf(x2, x2, fmaf(y2, y2, z2 * z2));
            sXY[tid] = make_ulonglong2(pack2(x1, x2), pack2(y1, y2));
            sZC[tid] = make_ulonglong2(pack2(z1, z2), pack2(c1, c2));
            sPA[tid] = make_ulonglong2(pack2(px1, px2), pack2(py1, py2));
            sPB[tid] = make_ulonglong2(pack2(pz1, pz2), 0ull);
        }
        __syncthreads();

        #pragma unroll 4
        for (int k = 0; k < JP; k++) {
            ulonglong2 q0 = sXY[k];
            ulonglong2 q1 = sZC[k];
            ulonglong2 q2 = sPA[k];
            ulonglong2 q3 = sPB[k];

            #pragma unroll
            for (int q = 0; q < IPT; q++) {
                u64 acc = fma2(X0[q], q0.x, q1.y);   // cj + 144.27*xi.xj
                acc = fma2(X1[q], q0.y, acc);
                acc = fma2(X2[q], q1.x, acc);
                u64 pd = mul2(P0[q], q2.x);          // pi.pj
                pd = fma2(P1[q], q2.y, pd);
                pd = fma2(P2[q], q3.x, pd);

                float a1, a2; unpack2(acc, a1, a2);
                u64 Gp = pack2(ex2a(a1), ex2a(a2));  // (G1,G2)
                u64 w  = mul2(Gp, pd);               // (w1,w2)

                awx[q] = fma2(w, q0.x, awx[q]);
                awy[q] = fma2(w, q0.y, awy[q]);
                awz[q] = fma2(w, q1.x, awz[q]);
                adx[q] = fma2(Gp, q2.x, adx[q]);
                ady[q] = fma2(Gp, q2.y, ady[q]);
                adz[q] = fma2(Gp, q3.x, adz[q]);
                arw[q] = add2(arw[q], w);
            }
        }
    }

    // combine j-parity halves, apply Ei, store partial
    #pragma unroll
    for (int q = 0; q < IPT; q++) {
        int i = bx * IPB + q * TI + tid;
        float e = Ei[q];
        float u, v;
        unpack2(adx[q], u, v); float dcx = e * (u + v);
        unpack2(ady[q], u, v); float dcy = e * (u + v);
        unpack2(adz[q], u, v); float dcz = e * (u + v);
        unpack2(awx[q], u, v); float wxx = e * (u + v);
        unpack2(awy[q], u, v); float wxy = e * (u + v);
        unpack2(awz[q], u, v); float wxz = e * (u + v);
        unpack2(arw[q], u, v); float row = e * (u + v);
        float4* p = (float4*)&g_part[(i * SPLITJ + jc) * 8];
        p[0] = make_float4(dcx, dcy, dcz, wxx);
        p[1] = make_float4(wxy, wxz, row, 0.0f);
    }

    // last CTA per i-block reduces the 32 split partials
    __threadfence();
    __syncthreads();
    if (tid == 0)
        sLast = (atomicAdd(&g_cnt[bx], 1) == SPLITJ - 1) ? 1 : 0;
    __syncthreads();
    if (!sLast) return;
    __threadfence();

    #pragma unroll
    for (int q = 0; q < IPT; q++) {
        int i = bx * IPB + q * TI + tid;
        float4 A = make_float4(0.f, 0.f, 0.f, 0.f);
        float4 B = make_float4(0.f, 0.f, 0.f, 0.f);
        #pragma unroll
        for (int s = 0; s < SPLITJ; s++) {
            const float4* p = (const float4*)&g_part[(i * SPLITJ + s) * 8];
            float4 a = p[0], b = p[1];
            A.x += a.x; A.y += a.y; A.z += a.z; A.w += a.w;
            B.x += b.x; B.y += b.y; B.z += b.z;
        }
        float xx = cp[3*i+0] - 0.5f, xy = cp[3*i+1] - 0.5f, xz = cp[3*i+2] - 0.5f;
        float row = B.z;
        out[3*i+0] = 100.0f * fmaf(xx, row, -A.w);   // translation-invariant
        out[3*i+1] = 100.0f * fmaf(xy, row, -B.x);
        out[3*i+2] = 100.0f * fmaf(xz, row, -B.y);
        out[3*N + 3*i+0] = A.x;
        out[3*N + 3*i+1] = A.y;
        out[3*N + 3*i+2] = A.z;
    }

    __syncthreads();
    if (tid == 0) g_cnt[bx] = 0;    // reset for next graph replay
}

extern "C" void kernel_launch(void* const* d_in, const int* in_sizes, int n_in,
                              void* d_out, int out_size)
{
    const float* mom = (const float*)d_in[0];
    const float* cp  = (const float*)d_in[1];
    float* out = (float*)d_out;
    int N = in_sizes[0] / 3;   // 8192

    dim3 g(N / IPB, SPLITJ);   // 64 x 32 = 2048 CTAs
    lddmm_fused<<<g, TI>>>(mom, cp, out, N);
}

// round 8
// speedup vs baseline: 1.1101x; 1.1101x over previous
#include <cuda_runtime.h>
#include <cuda_bf16.h>

// LDDMM variational evolve, Gaussian kernel sigma=0.1 (N=8192, D=3).
//   p      = clamp(mom, -1, 1)
//   K_ij   = exp(-50 |x_i - x_j|^2)
//   dcp_i  = sum_j K_ij p_j
//   dmom_i = 100 * ( x_i * sum_j W_ij - sum_j W_ij x_j ),  W_ij = K_ij (p_i.p_j)
//
// R8: occupancy fix over R7 (ncu: occ 23.3%, issue 51.5% -- latency-bound on
//     94-reg 64-thread CTAs). IPT=1, TI=128, launch_bounds(128,8) caps 64 regs
//     -> 32 warps/SM theoretical; grid 64x16=1024 CTAs all resident (43% occ).
//     Inner loop unchanged from R7: f32x2 lanes pack TWO j's (each accum fma2
//     retires 2 pairs), K = Ei * ex2(cj + xi.xj) on centered coords, Ei
//     factored into the epilogue. Fused: last CTA per i-block reduces the 16
//     split partials (fixed order, deterministic) and writes out.

#define TI      128
#define IPB     128          // i's per block (= TI, one i per thread)
#define JT      256          // j's per smem tile
#define JP      128          // j-pairs per tile (= TI)
#define SPLITJ  16
#define MAXN    8192
#define NBLK    (MAXN/IPB)   // 64 i-blocks
#define L2E     1.4426950408889634f

typedef unsigned long long u64;

// partials: [i][split][8]  (7 used: dcx dcy dcz wxx | wxy wxz row pad)
__device__ float g_part[MAXN * SPLITJ * 8];
__device__ int   g_cnt[NBLK];   // zero-init; self-resetting

__device__ __forceinline__ u64 pack2(float lo, float hi) {
    u64 r; asm("mov.b64 %0, {%1, %2};" : "=l"(r) : "f"(lo), "f"(hi)); return r;
}
__device__ __forceinline__ void unpack2(u64 v, float& lo, float& hi) {
    asm("mov.b64 {%0, %1}, %2;" : "=f"(lo), "=f"(hi) : "l"(v));
}
__device__ __forceinline__ u64 fma2(u64 a, u64 b, u64 c) {
    u64 d; asm("fma.rn.f32x2 %0, %1, %2, %3;" : "=l"(d) : "l"(a), "l"(b), "l"(c)); return d;
}
__device__ __forceinline__ u64 mul2(u64 a, u64 b) {
    u64 d; asm("mul.rn.f32x2 %0, %1, %2;" : "=l"(d) : "l"(a), "l"(b)); return d;
}
__device__ __forceinline__ u64 add2(u64 a, u64 b) {
    u64 d; asm("add.rn.f32x2 %0, %1, %2;" : "=l"(d) : "l"(a), "l"(b)); return d;
}
__device__ __forceinline__ float ex2a(float x) {
    float y; asm("ex2.approx.f32 %0, %1;" : "=f"(y) : "f"(x)); return y;
}
__device__ __forceinline__ float clamp1(float v) {
    return fminf(fmaxf(v, -1.f), 1.f);
}

__global__ void __launch_bounds__(TI, 8)
lddmm_fused(const float* __restrict__ mom,
            const float* __restrict__ cp,
            float* __restrict__ out,
            int N)
{
    // per j-pair: sXY=((x1,x2),(y1,y2)) sZC=((z1,z2),(c1,c2))
    //             sPA=((px1,px2),(py1,py2)) sPB=((pz1,pz2),-)
    __shared__ ulonglong2 sXY[JP], sZC[JP], sPA[JP], sPB[JP];
    __shared__ int sLast;

    const int bx = blockIdx.x;           // i-block
    const int jc = blockIdx.y;           // j-split
    const int jchunk = N / SPLITJ;       // 512
    const int j0 = jc * jchunk;
    const int tid = threadIdx.x;
    const int i  = bx * IPB + tid;

    const float c100 = 100.0f * L2E;
    const float cm50 = -50.0f * L2E;

    // per-i state (centered coords)
    u64 X0, X1, X2;       // (c100*xi_c, c100*xi_c)
    u64 P0, P1, P2;       // (pi_c, pi_c)
    float Ei;
    {
        float xx = cp[3*i+0] - 0.5f, xy = cp[3*i+1] - 0.5f, xz = cp[3*i+2] - 0.5f;
        float px = clamp1(mom[3*i+0]), py = clamp1(mom[3*i+1]), pz = clamp1(mom[3*i+2]);
        float sq = fmaf(xx, xx, fmaf(xy, xy, xz * xz));
        Ei = ex2a(cm50 * sq);
        X0 = pack2(c100 * xx, c100 * xx);
        X1 = pack2(c100 * xy, c100 * xy);
        X2 = pack2(c100 * xz, c100 * xz);
        P0 = pack2(px, px);
        P1 = pack2(py, py);
        P2 = pack2(pz, pz);
    }

    u64 awx = 0, awy = 0, awz = 0;    // j-parity sums of w*xj_c
    u64 adx = 0, ady = 0, adz = 0;    // j-parity sums of G*pj_c
    u64 arw = 0;                      // j-parity sums of w

    for (int jt = j0; jt < j0 + jchunk; jt += JT) {
        __syncthreads();
        {   // thread t stages j-pair (jt+2t, jt+2t+1);  TI == JP
            int j = jt + 2 * tid;
            float x1 = cp[3*j+0] - 0.5f, y1 = cp[3*j+1] - 0.5f, z1 = cp[3*j+2] - 0.5f;
            float x2 = cp[3*j+3] - 0.5f, y2 = cp[3*j+4] - 0.5f, z2 = cp[3*j+5] - 0.5f;
            float px1 = clamp1(mom[3*j+0]), py1 = clamp1(mom[3*j+1]), pz1 = clamp1(mom[3*j+2]);
            float px2 = clamp1(mom[3*j+3]), py2 = clamp1(mom[3*j+4]), pz2 = clamp1(mom[3*j+5]);
            float c1 = cm50 * fmaf(x1, x1, fmaf(y1, y1, z1 * z1));
            float c2 = cm50 * fmaf(x2, x2, fmaf(y2, y2, z2 * z2));
            sXY[tid] = make_ulonglong2(pack2(x1, x2), pack2(y1, y2));
            sZC[tid] = make_ulonglong2(pack2(z1, z2), pack2(c1, c2));
            sPA[tid] = make_ulonglong2(pack2(px1, px2), pack2(py1, py2));
            sPB[tid] = make_ulonglong2(pack2(pz1, pz2), 0ull);
        }
        __syncthreads();

        #pragma unroll 4
        for (int k = 0; k < JP; k++) {
            ulonglong2 q0 = sXY[k];
            ulonglong2 q1 = sZC[k];
            ulonglong2 q2 = sPA[k];
            ulonglong2 q3 = sPB[k];

            u64 acc = fma2(X0, q0.x, q1.y);   // cj + 144.27*xi.xj
            acc = fma2(X1, q0.y, acc);
            acc = fma2(X2, q1.x, acc);
            u64 pd = mul2(P0, q2.x);          // pi.pj
            pd = fma2(P1, q2.y, pd);
            pd = fma2(P2, q3.x, pd);

            float a1, a2; unpack2(acc, a1, a2);
            u64 Gp = pack2(ex2a(a1), ex2a(a2));  // (G1,G2)
            u64 w  = mul2(Gp, pd);               // (w1,w2)

            awx = fma2(w, q0.x, awx);
            awy = fma2(w, q0.y, awy);
            awz = fma2(w, q1.x, awz);
            adx = fma2(Gp, q2.x, adx);
            ady = fma2(Gp, q2.y, ady);
            adz = fma2(Gp, q3.x, adz);
            arw = add2(arw, w);
        }
    }

    // combine j-parity halves, apply Ei, store partial
    {
        float u, v;
        unpack2(adx, u, v); float dcx = Ei * (u + v);
        unpack2(ady, u, v); float dcy = Ei * (u + v);
        unpack2(adz, u, v); float dcz = Ei * (u + v);
        unpack2(awx, u, v); float wxx = Ei * (u + v);
        unpack2(awy, u, v); float wxy = Ei * (u + v);
        unpack2(awz, u, v); float wxz = Ei * (u + v);
        unpack2(arw, u, v); float row = Ei * (u + v);
        float4* p = (float4*)&g_part[(i * SPLITJ + jc) * 8];
        p[0] = make_float4(dcx, dcy, dcz, wxx);
        p[1] = make_float4(wxy, wxz, row, 0.0f);
    }

    // last CTA per i-block reduces the 16 split partials
    __threadfence();
    __syncthreads();
    if (tid == 0)
        sLast = (atomicAdd(&g_cnt[bx], 1) == SPLITJ - 1) ? 1 : 0;
    __syncthreads();
    if (!sLast) return;
    __threadfence();

    {
        float4 A = make_float4(0.f, 0.f, 0.f, 0.f);
        float4 B = make_float4(0.f, 0.f, 0.f, 0.f);
        #pragma unroll
        for (int s = 0; s < SPLITJ; s++) {
            const float4* p = (const float4*)&g_part[(i * SPLITJ + s) * 8];
            float4 a = p[0], b = p[1];
            A.x += a.x; A.y += a.y; A.z += a.z; A.w += a.w;
            B.x += b.x; B.y += b.y; B.z += b.z;
        }
        float xx = cp[3*i+0] - 0.5f, xy = cp[3*i+1] - 0.5f, xz = cp[3*i+2] - 0.5f;
        float row = B.z;
        out[3*i+0] = 100.0f * fmaf(xx, row, -A.w);   // translation-invariant
        out[3*i+1] = 100.0f * fmaf(xy, row, -B.x);
        out[3*i+2] = 100.0f * fmaf(xz, row, -B.y);
        out[3*N + 3*i+0] = A.x;
        out[3*N + 3*i+1] = A.y;
        out[3*N + 3*i+2] = A.z;
    }

    __syncthreads();
    if (tid == 0) g_cnt[bx] = 0;    // reset for next graph replay
}

extern "C" void kernel_launch(void* const* d_in, const int* in_sizes, int n_in,
                              void* d_out, int out_size)
{
    const float* mom = (const float*)d_in[0];
    const float* cp  = (const float*)d_in[1];
    float* out = (float*)d_out;
    int N = in_sizes[0] / 3;   // 8192

    dim3 g(N / IPB, SPLITJ);   // 64 x 16 = 1024 CTAs, all resident in one wave
    lddmm_fused<<<g, TI>>>(mom, cp, out, N);
}

// round 9
// speedup vs baseline: 1.1980x; 1.0792x over previous
#include <cuda_runtime.h>
#include <cuda_bf16.h>

// LDDMM variational evolve, Gaussian kernel sigma=0.1 (N=8192, D=3).
//   p      = clamp(mom, -1, 1)
//   K_ij   = exp(-50 |x_i - x_j|^2)
//   dcp_i  = sum_j K_ij p_j
//   dmom_i = 100 * ( x_i * sum_j W_ij - sum_j W_ij x_j ),  W_ij = K_ij (p_i.p_j)
//
// R9: latency-hiding rebuild of R8 (ncu: issue 52.5%, occ 28.9% -- LDS+chain
//     latency exposed by the 64-reg pipelining squeeze):
//     - launch_bounds(128,7): 73 regs, warp cap 28/SM == grid supply 27.7.
//     - ONE smem tile per CTA (512 j's = 256 pairs, 14.4KB): no outer loop,
//       single __syncthreads, straight 256-iter inner loop.
//     - explicit prefetch-1 on the smem operands (+1 pad entry).
//     - 7-u64 smem record: 3x LDS.128 + 1x LDS.64 per iter.
//     Inner math unchanged: f32x2 lanes pack TWO j's, K = Ei*ex2(cj+xi.xj) on
//     centered coords, Ei folded into the epilogue. Fused last-CTA reduction.

#define TI      128
#define IPB     128          // i's per block (one i per thread)
#define JP      256          // j-pairs per CTA (= jchunk/2)
#define SPLITJ  16
#define MAXN    8192
#define NBLK    (MAXN/IPB)   // 64 i-blocks
#define L2E     1.4426950408889634f

typedef unsigned long long u64;

// partials: [i][split][8]  (7 used: dcx dcy dcz wxx | wxy wxz row pad)
__device__ float g_part[MAXN * SPLITJ * 8];
__device__ int   g_cnt[NBLK];   // zero-init; self-resetting

__device__ __forceinline__ u64 pack2(float lo, float hi) {
    u64 r; asm("mov.b64 %0, {%1, %2};" : "=l"(r) : "f"(lo), "f"(hi)); return r;
}
__device__ __forceinline__ void unpack2(u64 v, float& lo, float& hi) {
    asm("mov.b64 {%0, %1}, %2;" : "=f"(lo), "=f"(hi) : "l"(v));
}
__device__ __forceinline__ u64 fma2(u64 a, u64 b, u64 c) {
    u64 d; asm("fma.rn.f32x2 %0, %1, %2, %3;" : "=l"(d) : "l"(a), "l"(b), "l"(c)); return d;
}
__device__ __forceinline__ u64 mul2(u64 a, u64 b) {
    u64 d; asm("mul.rn.f32x2 %0, %1, %2;" : "=l"(d) : "l"(a), "l"(b)); return d;
}
__device__ __forceinline__ u64 add2(u64 a, u64 b) {
    u64 d; asm("add.rn.f32x2 %0, %1, %2;" : "=l"(d) : "l"(a), "l"(b)); return d;
}
__device__ __forceinline__ float ex2a(float x) {
    float y; asm("ex2.approx.f32 %0, %1;" : "=f"(y) : "f"(x)); return y;
}
__device__ __forceinline__ float clamp1(float v) {
    return fminf(fmaxf(v, -1.f), 1.f);
}

__global__ void __launch_bounds__(TI, 7)
lddmm_fused(const float* __restrict__ mom,
            const float* __restrict__ cp,
            float* __restrict__ out,
            int N)
{
    // per j-pair: sA=((x1,x2),(y1,y2))  sB=((z1,z2),(c1,c2))
    //             sC=((px1,px2),(py1,py2))  sZ=(pz1,pz2)
    __shared__ ulonglong2 sA[JP + 1], sB[JP + 1], sC[JP + 1];
    __shared__ u64 sZ[JP + 1];
    __shared__ int sLast;

    const int bx = blockIdx.x;           // i-block
    const int jc = blockIdx.y;           // j-split
    const int j0 = jc * (N / SPLITJ);    // jchunk = 512
    const int tid = threadIdx.x;
    const int i  = bx * IPB + tid;

    const float c100 = 100.0f * L2E;
    const float cm50 = -50.0f * L2E;

    // per-i state (centered coords)
    u64 X0, X1, X2, P0, P1, P2;
    float Ei;
    {
        float xx = cp[3*i+0] - 0.5f, xy = cp[3*i+1] - 0.5f, xz = cp[3*i+2] - 0.5f;
        float px = clamp1(mom[3*i+0]), py = clamp1(mom[3*i+1]), pz = clamp1(mom[3*i+2]);
        float sq = fmaf(xx, xx, fmaf(xy, xy, xz * xz));
        Ei = ex2a(cm50 * sq);
        X0 = pack2(c100 * xx, c100 * xx);
        X1 = pack2(c100 * xy, c100 * xy);
        X2 = pack2(c100 * xz, c100 * xz);
        P0 = pack2(px, px);
        P1 = pack2(py, py);
        P2 = pack2(pz, pz);
    }

    // stage the full 256-pair tile; thread t handles pairs t and t+TI;
    // thread 0 duplicates pair 0 into the prefetch pad slot [JP].
    #pragma unroll
    for (int t = tid; t < JP; t += TI) {
        int j = j0 + 2 * t;
        float x1 = cp[3*j+0] - 0.5f, y1 = cp[3*j+1] - 0.5f, z1 = cp[3*j+2] - 0.5f;
        float x2 = cp[3*j+3] - 0.5f, y2 = cp[3*j+4] - 0.5f, z2 = cp[3*j+5] - 0.5f;
        float px1 = clamp1(mom[3*j+0]), py1 = clamp1(mom[3*j+1]), pz1 = clamp1(mom[3*j+2]);
        float px2 = clamp1(mom[3*j+3]), py2 = clamp1(mom[3*j+4]), pz2 = clamp1(mom[3*j+5]);
        float c1 = cm50 * fmaf(x1, x1, fmaf(y1, y1, z1 * z1));
        float c2 = cm50 * fmaf(x2, x2, fmaf(y2, y2, z2 * z2));
        ulonglong2 vA = make_ulonglong2(pack2(x1, x2), pack2(y1, y2));
        ulonglong2 vB = make_ulonglong2(pack2(z1, z2), pack2(c1, c2));
        ulonglong2 vC = make_ulonglong2(pack2(px1, px2), pack2(py1, py2));
        u64 vZ = pack2(pz1, pz2);
        sA[t] = vA; sB[t] = vB; sC[t] = vC; sZ[t] = vZ;
        if (t == 0) { sA[JP] = vA; sB[JP] = vB; sC[JP] = vC; sZ[JP] = vZ; }
    }
    __syncthreads();

    u64 awx = 0, awy = 0, awz = 0;    // j-parity sums of w*xj_c
    u64 adx = 0, ady = 0, adz = 0;    // j-parity sums of G*pj_c
    u64 arw = 0;                      // j-parity sums of w

    // prefetch-1 pipelined inner loop
    ulonglong2 cA = sA[0], cB = sB[0], cC = sC[0];
    u64 cZ = sZ[0];

    #pragma unroll 4
    for (int k = 0; k < JP; k++) {
        ulonglong2 nA = sA[k+1], nB = sB[k+1], nC = sC[k+1];
        u64 nZ = sZ[k+1];

        u64 acc = fma2(X0, cA.x, cB.y);   // cj + 144.27*xi.xj
        acc = fma2(X1, cA.y, acc);
        acc = fma2(X2, cB.x, acc);
        u64 pd = mul2(P0, cC.x);          // pi.pj
        pd = fma2(P1, cC.y, pd);
        pd = fma2(P2, cZ, pd);

        float a1, a2; unpack2(acc, a1, a2);
        u64 Gp = pack2(ex2a(a1), ex2a(a2));  // (G1,G2)
        u64 w  = mul2(Gp, pd);               // (w1,w2)

        awx = fma2(w, cA.x, awx);
        awy = fma2(w, cA.y, awy);
        awz = fma2(w, cB.x, awz);
        adx = fma2(Gp, cC.x, adx);
        ady = fma2(Gp, cC.y, ady);
        adz = fma2(Gp, cZ, adz);
        arw = add2(arw, w);

        cA = nA; cB = nB; cC = nC; cZ = nZ;
    }

    // combine j-parity halves, apply Ei, store partial
    {
        float u, v;
        unpack2(adx, u, v); float dcx = Ei * (u + v);
        unpack2(ady, u, v); float dcy = Ei * (u + v);
        unpack2(adz, u, v); float dcz = Ei * (u + v);
        unpack2(awx, u, v); float wxx = Ei * (u + v);
        unpack2(awy, u, v); float wxy = Ei * (u + v);
        unpack2(awz, u, v); float wxz = Ei * (u + v);
        unpack2(arw, u, v); float row = Ei * (u + v);
        float4* p = (float4*)&g_part[(i * SPLITJ + jc) * 8];
        p[0] = make_float4(dcx, dcy, dcz, wxx);
        p[1] = make_float4(wxy, wxz, row, 0.0f);
    }

    // last CTA per i-block reduces the 16 split partials (fixed order)
    __threadfence();
    __syncthreads();
    if (tid == 0)
        sLast = (atomicAdd(&g_cnt[bx], 1) == SPLITJ - 1) ? 1 : 0;
    __syncthreads();
    if (!sLast) return;
    __threadfence();

    {
        float4 A = make_float4(0.f, 0.f, 0.f, 0.f);
        float4 B = make_float4(0.f, 0.f, 0.f, 0.f);
        #pragma unroll
        for (int s = 0; s < SPLITJ; s++) {
            const float4* p = (const float4*)&g_part[(i * SPLITJ + s) * 8];
            float4 a = p[0], b = p[1];
            A.x += a.x; A.y += a.y; A.z += a.z; A.w += a.w;
            B.x += b.x; B.y += b.y; B.z += b.z;
        }
        float xx = cp[3*i+0] - 0.5f, xy = cp[3*i+1] - 0.5f, xz = cp[3*i+2] - 0.5f;
        float row = B.z;
        out[3*i+0] = 100.0f * fmaf(xx, row, -A.w);   // translation-invariant
        out[3*i+1] = 100.0f * fmaf(xy, row, -B.x);
        out[3*i+2] = 100.0f * fmaf(xz, row, -B.y);
        out[3*N + 3*i+0] = A.x;
        out[3*N + 3*i+1] = A.y;
        out[3*N + 3*i+2] = A.z;
    }

    __syncthreads();
    if (tid == 0) g_cnt[bx] = 0;    // reset for next graph replay
}

extern "C" void kernel_launch(void* const* d_in, const int* in_sizes, int n_in,
                              void* d_out, int out_size)
{
    const float* mom = (const float*)d_in[0];
    const float* cp  = (const float*)d_in[1];
    float* out = (float*)d_out;
    int N = in_sizes[0] / 3;   // 8192

    dim3 g(N / IPB, SPLITJ);   // 64 x 16 = 1024 CTAs, single resident wave
    lddmm_fused<<<g, TI>>>(mom, cp, out, N);
}